// round 5
// baseline (speedup 1.0000x reference)
#include <cuda_runtime.h>
#include <cuda_bf16.h>
#include <cstdint>

// Problem constants
#define B_ 4
#define S_ 2048
#define D_ 1024
#define H_ 16
#define DK_ 64
#define SCALE_ 0.125f   // 1/sqrt(64)

#define M_ROWS (B_ * S_)   // 8192

// ---------------- scratch (device globals; no allocation allowed) ----------
__device__ uint32_t g_qin[B_ * S_ * D_];
__device__ uint32_t g_kin[B_ * S_ * D_];
__device__ uint32_t g_vin[B_ * S_ * D_];
__device__ uint32_t g_wq[D_ * D_];
__device__ uint32_t g_wk[D_ * D_];
__device__ uint32_t g_wv[D_ * D_];
__device__ uint32_t g_wo[D_ * D_];
__device__ uint32_t g_q[B_ * H_ * S_ * DK_];    // [B,H,S,DK], pre-scaled
__device__ uint32_t g_k[B_ * H_ * S_ * DK_];
__device__ uint32_t g_v[B_ * H_ * S_ * DK_];
__device__ uint32_t g_att[B_ * S_ * D_];        // [B,S,D]

// ---------------- helpers -----------------------------------------------------
__device__ __forceinline__ uint32_t f2tf32(float f) {
    uint32_t r;
    asm("cvt.rna.tf32.f32 %0, %1;" : "=r"(r) : "f"(f));
    return r;
}

__device__ __forceinline__ void mma_tf32_16x8x8(
    float& c0, float& c1, float& c2, float& c3,
    uint32_t a0, uint32_t a1, uint32_t a2, uint32_t a3,
    uint32_t b0, uint32_t b1)
{
    asm volatile(
        "mma.sync.aligned.m16n8k8.row.col.f32.tf32.tf32.f32 "
        "{%0,%1,%2,%3}, {%4,%5,%6,%7}, {%8,%9}, {%0,%1,%2,%3};"
        : "+f"(c0), "+f"(c1), "+f"(c2), "+f"(c3)
        : "r"(a0), "r"(a1), "r"(a2), "r"(a3), "r"(b0), "r"(b1));
}

__device__ __forceinline__ void cp_async16(uint32_t smem_dst, const void* gsrc) {
    asm volatile("cp.async.cg.shared.global [%0], [%1], 16;"
                 :: "r"(smem_dst), "l"(gsrc));
}
__device__ __forceinline__ void cp_commit() {
    asm volatile("cp.async.commit_group;");
}
__device__ __forceinline__ void cp_wait0() {
    asm volatile("cp.async.wait_group 0;");
}
__device__ __forceinline__ uint32_t smaddr(const void* p) {
    return (uint32_t)__cvta_generic_to_shared(p);
}

// ---------------- fp32 -> tf32 conversion kernel ------------------------------
__global__ __launch_bounds__(256)
void conv_tf32_kernel(const float4* __restrict__ in, uint4* __restrict__ out, int n4)
{
    const int i = blockIdx.x * 256 + threadIdx.x;
    if (i < n4) {
        float4 v = in[i];
        uint4 r;
        r.x = f2tf32(v.x); r.y = f2tf32(v.y);
        r.z = f2tf32(v.z); r.w = f2tf32(v.w);
        out[i] = r;
    }
}

// ---------------- tf32 tensor-core GEMM (cp.async, GBK=32, 2-stage) -----------
#define GBM 128
#define GBN 128
#define GBK 32
#define AS_STR (GBK + 4)    // 36: frag bank (4*lr+lc)%32 conflict-free
#define BS_STR (GBN + 8)    // 136
#define AS_WORDS (GBM * AS_STR)   // 4608
#define BS_WORDS (GBK * BS_STR)   // 4352
#define GEMM_SMEM ((2 * AS_WORDS + 2 * BS_WORDS) * 4)   // 71,680 B

template <int MODE>
__global__ __launch_bounds__(256)
void gemm_tf32_kernel(const uint32_t* __restrict__ A, const uint32_t* __restrict__ W,
                      const float* __restrict__ bias, void* __restrict__ Cout,
                      int M, int N, int K, float out_scale)
{
    extern __shared__ uint32_t gsm[];
    uint32_t* As = gsm;                     // 2 stages
    uint32_t* Bs = gsm + 2 * AS_WORDS;

    const int tid  = threadIdx.x;
    const int warp = tid >> 5;
    const int lane = tid & 31;
    const int warpM = warp >> 2;
    const int warpN = warp & 3;
    const int lr = lane >> 2;
    const int lc = lane & 3;

    const int block_row = blockIdx.y;
    const int block_col = blockIdx.x;

    const uint32_t* Ab = A + (size_t)block_row * GBM * K;
    const uint32_t* Wb = W + block_col * GBN;

    float acc[4][4][4];
    #pragma unroll
    for (int mt = 0; mt < 4; mt++)
        #pragma unroll
        for (int nt = 0; nt < 4; nt++)
            #pragma unroll
            for (int r = 0; r < 4; r++) acc[mt][nt][r] = 0.f;

    // stage loader: A 128x32 = 1024 chunks, B 32x128 = 1024 chunks; 4+4/thread
    auto load_stage = [&](int k0, int buf) {
        uint32_t* Ad = As + buf * AS_WORDS;
        uint32_t* Bd = Bs + buf * BS_WORDS;
        #pragma unroll
        for (int u = 0; u < 4; u++) {
            const int flat = tid + u * 256;
            const int ar = flat >> 3, ac = (flat & 7) * 4;
            cp_async16(smaddr(Ad + ar * AS_STR + ac),
                       Ab + (size_t)ar * K + k0 + ac);
            const int br = flat >> 5, bc = (flat & 31) * 4;
            cp_async16(smaddr(Bd + br * BS_STR + bc),
                       Wb + (size_t)(k0 + br) * N + bc);
        }
    };

    const int NK = K / GBK;
    load_stage(0, 0);
    cp_commit();

    for (int it = 0; it < NK; it++) {
        cp_wait0();
        __syncthreads();
        if (it + 1 < NK) { load_stage((it + 1) * GBK, (it + 1) & 1); cp_commit(); }

        const uint32_t* As_s = As + (it & 1) * AS_WORDS;
        const uint32_t* Bs_s = Bs + (it & 1) * BS_WORDS;

        #pragma unroll
        for (int ks = 0; ks < GBK; ks += 8) {
            uint32_t af[4][4];
            #pragma unroll
            for (int mt = 0; mt < 4; mt++) {
                const int m0 = warpM * 64 + mt * 16;
                af[mt][0] = As_s[(m0 + lr)     * AS_STR + ks + lc];
                af[mt][1] = As_s[(m0 + 8 + lr) * AS_STR + ks + lc];
                af[mt][2] = As_s[(m0 + lr)     * AS_STR + ks + 4 + lc];
                af[mt][3] = As_s[(m0 + 8 + lr) * AS_STR + ks + 4 + lc];
            }
            uint32_t bf[4][2];
            #pragma unroll
            for (int nt = 0; nt < 4; nt++) {
                const int n0 = warpN * 32 + nt * 8;
                bf[nt][0] = Bs_s[(ks + lc)     * BS_STR + n0 + lr];
                bf[nt][1] = Bs_s[(ks + 4 + lc) * BS_STR + n0 + lr];
            }
            #pragma unroll
            for (int mt = 0; mt < 4; mt++)
                #pragma unroll
                for (int nt = 0; nt < 4; nt++)
                    mma_tf32_16x8x8(acc[mt][nt][0], acc[mt][nt][1],
                                    acc[mt][nt][2], acc[mt][nt][3],
                                    af[mt][0], af[mt][1], af[mt][2], af[mt][3],
                                    bf[nt][0], bf[nt][1]);
        }
    }

    #pragma unroll
    for (int mt = 0; mt < 4; mt++) {
        #pragma unroll
        for (int nt = 0; nt < 4; nt++) {
            const int n = block_col * GBN + warpN * 32 + nt * 8 + lc * 2;
            #pragma unroll
            for (int half = 0; half < 2; half++) {
                const int m = block_row * GBM + warpM * 64 + mt * 16 + lr + half * 8;
                const float v0 = acc[mt][nt][half * 2 + 0] + bias[n];
                const float v1 = acc[mt][nt][half * 2 + 1] + bias[n + 1];
                if (MODE == 0) {
                    float* C = (float*)Cout;
                    *(float2*)&C[(size_t)m * N + n] = make_float2(v0, v1);
                } else {
                    uint32_t* C = (uint32_t*)Cout;
                    const int b  = m >> 11;
                    const int s  = m & 2047;
                    const int h  = n >> 6;
                    const int dk = n & 63;
                    uint2 w;
                    w.x = f2tf32(v0 * out_scale);
                    w.y = f2tf32(v1 * out_scale);
                    *(uint2*)(C + (((size_t)(b * H_ + h)) * S_ + s) * DK_ + dk) = w;
                }
            }
        }
    }
}

// ---------------- tensor-core causal flash attention (tf32) -------------------
// 128 q-rows per block, 8 warps x 16 rows, 64-key double-buffered tiles,
// warp-private P buffers (no block barrier between softmax and PV mma).
#define FAP 68
#define KTILE_W (64 * FAP)                 // 4352 words
#define FA_SMEM ((4 * KTILE_W + 128 * FAP) * 4)   // 104,448 B

__global__ __launch_bounds__(256)
void flash_attn_tc_kernel(const uint32_t* __restrict__ q, const uint32_t* __restrict__ k,
                          const uint32_t* __restrict__ v, uint32_t* __restrict__ o)
{
    extern __shared__ uint32_t sm[];
    uint32_t* KsBuf[2] = { sm,               sm + KTILE_W };
    uint32_t* VsBuf[2] = { sm + 2 * KTILE_W, sm + 3 * KTILE_W };
    uint32_t* Pbase    = sm + 4 * KTILE_W;   // 128 x FAP, warp-private slices

    const int qt  = gridDim.x - 1 - blockIdx.x;   // big blocks first
    const int bh  = blockIdx.y;
    const int tid = threadIdx.x;
    const int warp = tid >> 5;
    const int lane = tid & 31;
    const int lr = lane >> 2;
    const int lc = lane & 3;
    const int q0 = qt * 128;
    const int mb = warp * 16;
    uint32_t* Pw = Pbase + warp * 16 * FAP;

    const uint32_t* qb = q + (size_t)bh * S_ * DK_;
    const uint32_t* kb = k + (size_t)bh * S_ * DK_;
    const uint32_t* vb = v + (size_t)bh * S_ * DK_;

    // ---- stage Q tile (128x64) into sm[0 .. 128*FAP) ----
    #pragma unroll
    for (int i = 0; i < 8; i++) {
        const int flat = tid + 256 * i;           // 0..2047
        const int row = flat >> 4;
        const int c4  = (flat & 15) * 4;
        cp_async16(smaddr(sm + row * FAP + c4), qb + (size_t)(q0 + row) * DK_ + c4);
    }
    cp_commit();
    cp_wait0();
    __syncthreads();

    uint32_t qf[8][4];
    #pragma unroll
    for (int i = 0; i < 8; i++) {
        qf[i][0] = sm[(mb + lr)     * FAP + 8 * i + lc];
        qf[i][1] = sm[(mb + 8 + lr) * FAP + 8 * i + lc];
        qf[i][2] = sm[(mb + lr)     * FAP + 8 * i + 4 + lc];
        qf[i][3] = sm[(mb + 8 + lr) * FAP + 8 * i + 4 + lc];
    }
    __syncthreads();   // Q reads done before K/V tiles overwrite

    float oacc[8][4];
    #pragma unroll
    for (int nt = 0; nt < 8; nt++)
        #pragma unroll
        for (int c = 0; c < 4; c++) oacc[nt][c] = 0.f;
    float mrow[2] = { -INFINITY, -INFINITY };
    float lrow[2] = { 0.f, 0.f };

    // tile copy: 64x64 words = 1024 16B-chunks; 4 per thread
    auto load_tile = [&](const uint32_t* gsrc, uint32_t* sdst) {
        #pragma unroll
        for (int i = 0; i < 4; i++) {
            const int flat = tid + 256 * i;
            const int row = flat >> 4;
            const int c4  = (flat & 15) * 4;
            cp_async16(smaddr(sdst + row * FAP + c4), gsrc + row * 64 + c4);
        }
    };

    const int NT = 2 * qt + 2;          // key tiles for this block
    const int rowmax = q0 + mb + 15;    // warp's last q row

    load_tile(kb, KsBuf[0]);
    load_tile(vb, VsBuf[0]);
    cp_commit();

    for (int kt = 0; kt < NT; kt++) {
        const int cur = kt & 1;
        cp_wait0();
        __syncthreads();
        if (kt + 1 < NT) {
            load_tile(kb + (size_t)(kt + 1) * 64 * DK_, KsBuf[cur ^ 1]);
            load_tile(vb + (size_t)(kt + 1) * 64 * DK_, VsBuf[cur ^ 1]);
            cp_commit();
        }
        const int k0 = kt * 64;
        if (k0 > rowmax) continue;       // tile entirely above warp's diagonal

        const uint32_t* Ks = KsBuf[cur];
        const uint32_t* Vs = VsBuf[cur];

        // ---- S = Q @ K^T ----
        float s[8][4];
        #pragma unroll
        for (int nt = 0; nt < 8; nt++) {
            s[nt][0] = s[nt][1] = s[nt][2] = s[nt][3] = 0.f;
            #pragma unroll
            for (int i = 0; i < 8; i++) {
                const uint32_t b0 = Ks[(nt * 8 + lr) * FAP + 8 * i + lc];
                const uint32_t b1 = Ks[(nt * 8 + lr) * FAP + 8 * i + 4 + lc];
                mma_tf32_16x8x8(s[nt][0], s[nt][1], s[nt][2], s[nt][3],
                                qf[i][0], qf[i][1], qf[i][2], qf[i][3], b0, b1);
            }
        }

        // ---- causal mask (tiles intersecting the warp's diagonal band) ----
        if (k0 + 63 > q0 + mb) {
            const int r0 = q0 + mb + lr;
            const int r1 = r0 + 8;
            #pragma unroll
            for (int nt = 0; nt < 8; nt++) {
                const int cg = k0 + nt * 8 + 2 * lc;
                if (cg     > r0) s[nt][0] = -1e30f;
                if (cg + 1 > r0) s[nt][1] = -1e30f;
                if (cg     > r1) s[nt][2] = -1e30f;
                if (cg + 1 > r1) s[nt][3] = -1e30f;
            }
        }

        // ---- online softmax ----
        float m0 = -INFINITY, m1 = -INFINITY;
        #pragma unroll
        for (int nt = 0; nt < 8; nt++) {
            m0 = fmaxf(m0, fmaxf(s[nt][0], s[nt][1]));
            m1 = fmaxf(m1, fmaxf(s[nt][2], s[nt][3]));
        }
        m0 = fmaxf(m0, __shfl_xor_sync(0xffffffffu, m0, 1));
        m0 = fmaxf(m0, __shfl_xor_sync(0xffffffffu, m0, 2));
        m1 = fmaxf(m1, __shfl_xor_sync(0xffffffffu, m1, 1));
        m1 = fmaxf(m1, __shfl_xor_sync(0xffffffffu, m1, 2));

        const float mnew0 = fmaxf(mrow[0], m0);
        const float mnew1 = fmaxf(mrow[1], m1);
        const float alpha0 = __expf(mrow[0] - mnew0);
        const float alpha1 = __expf(mrow[1] - mnew1);
        float ls0 = 0.f, ls1 = 0.f;
        #pragma unroll
        for (int nt = 0; nt < 8; nt++) {
            s[nt][0] = __expf(s[nt][0] - mnew0);
            s[nt][1] = __expf(s[nt][1] - mnew0);
            s[nt][2] = __expf(s[nt][2] - mnew1);
            s[nt][3] = __expf(s[nt][3] - mnew1);
            ls0 += s[nt][0] + s[nt][1];
            ls1 += s[nt][2] + s[nt][3];
        }
        ls0 += __shfl_xor_sync(0xffffffffu, ls0, 1);
        ls0 += __shfl_xor_sync(0xffffffffu, ls0, 2);
        ls1 += __shfl_xor_sync(0xffffffffu, ls1, 1);
        ls1 += __shfl_xor_sync(0xffffffffu, ls1, 2);
        lrow[0] = lrow[0] * alpha0 + ls0;
        lrow[1] = lrow[1] * alpha1 + ls1;
        mrow[0] = mnew0;
        mrow[1] = mnew1;
        #pragma unroll
        for (int nt = 0; nt < 8; nt++) {
            oacc[nt][0] *= alpha0; oacc[nt][1] *= alpha0;
            oacc[nt][2] *= alpha1; oacc[nt][3] *= alpha1;
        }

        // ---- store P (tf32) into warp-private buffer ----
        #pragma unroll
        for (int nt = 0; nt < 8; nt++) {
            const int c = nt * 8 + 2 * lc;
            uint2 w0, w1;
            w0.x = f2tf32(s[nt][0]); w0.y = f2tf32(s[nt][1]);
            w1.x = f2tf32(s[nt][2]); w1.y = f2tf32(s[nt][3]);
            *(uint2*)(Pw + lr       * FAP + c) = w0;
            *(uint2*)(Pw + (8 + lr) * FAP + c) = w1;
        }
        __syncwarp();

        // ---- O += P @ V ----
        #pragma unroll
        for (int i = 0; i < 8; i++) {
            uint32_t pf[4];
            pf[0] = Pw[lr       * FAP + 8 * i + lc];
            pf[1] = Pw[(8 + lr) * FAP + 8 * i + lc];
            pf[2] = Pw[lr       * FAP + 8 * i + 4 + lc];
            pf[3] = Pw[(8 + lr) * FAP + 8 * i + 4 + lc];
            #pragma unroll
            for (int nt = 0; nt < 8; nt++) {
                const uint32_t b0 = Vs[(8 * i + lc)     * FAP + nt * 8 + lr];
                const uint32_t b1 = Vs[(8 * i + 4 + lc) * FAP + nt * 8 + lr];
                mma_tf32_16x8x8(oacc[nt][0], oacc[nt][1], oacc[nt][2], oacc[nt][3],
                                pf[0], pf[1], pf[2], pf[3], b0, b1);
            }
        }
    }

    // ---- finalize & write tf32 bits to [B,S,D] ----
    const float inv0 = 1.f / lrow[0];
    const float inv1 = 1.f / lrow[1];
    const int b = bh >> 4;
    const int h = bh & 15;
    const int r0 = q0 + mb + lr;
    uint32_t* ob0 = o + ((size_t)b * S_ + r0)     * D_ + h * DK_;
    uint32_t* ob1 = o + ((size_t)b * S_ + r0 + 8) * D_ + h * DK_;
    #pragma unroll
    for (int nt = 0; nt < 8; nt++) {
        const int c = nt * 8 + 2 * lc;
        uint2 w0, w1;
        w0.x = f2tf32(oacc[nt][0] * inv0); w0.y = f2tf32(oacc[nt][1] * inv0);
        w1.x = f2tf32(oacc[nt][2] * inv1); w1.y = f2tf32(oacc[nt][3] * inv1);
        *(uint2*)(ob0 + c) = w0;
        *(uint2*)(ob1 + c) = w1;
    }
}

// ---------------- launch ------------------------------------------------------
extern "C" void kernel_launch(void* const* d_in, const int* in_sizes, int n_in,
                              void* d_out, int out_size)
{
    const float* Q  = (const float*)d_in[0];
    const float* K  = (const float*)d_in[1];
    const float* V  = (const float*)d_in[2];
    const float* Wq = (const float*)d_in[3];
    const float* bq = (const float*)d_in[4];
    const float* Wk = (const float*)d_in[5];
    const float* bk = (const float*)d_in[6];
    const float* Wv = (const float*)d_in[7];
    const float* bv = (const float*)d_in[8];
    const float* Wo = (const float*)d_in[9];
    const float* bo = (const float*)d_in[10];
    // d_in[11] = mask (causal, known statically; ignored)

    uint32_t *qin, *kin, *vin, *wq, *wk, *wv, *wo, *q, *k, *v, *att;
    cudaGetSymbolAddress((void**)&qin, g_qin);
    cudaGetSymbolAddress((void**)&kin, g_kin);
    cudaGetSymbolAddress((void**)&vin, g_vin);
    cudaGetSymbolAddress((void**)&wq,  g_wq);
    cudaGetSymbolAddress((void**)&wk,  g_wk);
    cudaGetSymbolAddress((void**)&wv,  g_wv);
    cudaGetSymbolAddress((void**)&wo,  g_wo);
    cudaGetSymbolAddress((void**)&q,   g_q);
    cudaGetSymbolAddress((void**)&k,   g_k);
    cudaGetSymbolAddress((void**)&v,   g_v);
    cudaGetSymbolAddress((void**)&att, g_att);

    // fp32 -> tf32 pre-conversion
    const int n4_in = (B_ * S_ * D_) / 4;
    const int n4_w  = (D_ * D_) / 4;
    conv_tf32_kernel<<<(n4_in + 255) / 256, 256>>>((const float4*)Q,  (uint4*)qin, n4_in);
    conv_tf32_kernel<<<(n4_in + 255) / 256, 256>>>((const float4*)K,  (uint4*)kin, n4_in);
    conv_tf32_kernel<<<(n4_in + 255) / 256, 256>>>((const float4*)V,  (uint4*)vin, n4_in);
    conv_tf32_kernel<<<(n4_w  + 255) / 256, 256>>>((const float4*)Wq, (uint4*)wq,  n4_w);
    conv_tf32_kernel<<<(n4_w  + 255) / 256, 256>>>((const float4*)Wk, (uint4*)wk,  n4_w);
    conv_tf32_kernel<<<(n4_w  + 255) / 256, 256>>>((const float4*)Wv, (uint4*)wv,  n4_w);
    conv_tf32_kernel<<<(n4_w  + 255) / 256, 256>>>((const float4*)Wo, (uint4*)wo,  n4_w);

    cudaFuncSetAttribute(gemm_tf32_kernel<0>,
                         cudaFuncAttributeMaxDynamicSharedMemorySize, GEMM_SMEM);
    cudaFuncSetAttribute(gemm_tf32_kernel<1>,
                         cudaFuncAttributeMaxDynamicSharedMemorySize, GEMM_SMEM);
    cudaFuncSetAttribute(flash_attn_tc_kernel,
                         cudaFuncAttributeMaxDynamicSharedMemorySize, FA_SMEM);

    const dim3 gemm_grid(D_ / GBN, M_ROWS / GBM);   // (8, 64)
    const dim3 gemm_block(256);

    // QKV projections -> tf32 [B,H,S,DK]; Q pre-scaled by 1/sqrt(dk)
    gemm_tf32_kernel<1><<<gemm_grid, gemm_block, GEMM_SMEM>>>(qin, wq, bq, q, M_ROWS, D_, D_, SCALE_);
    gemm_tf32_kernel<1><<<gemm_grid, gemm_block, GEMM_SMEM>>>(kin, wk, bk, k, M_ROWS, D_, D_, 1.0f);
    gemm_tf32_kernel<1><<<gemm_grid, gemm_block, GEMM_SMEM>>>(vin, wv, bv, v, M_ROWS, D_, D_, 1.0f);

    // causal flash attention -> tf32 [B,S,D]
    const dim3 fa_grid(S_ / 128, B_ * H_);          // (16, 64)
    flash_attn_tc_kernel<<<fa_grid, 256, FA_SMEM>>>(q, k, v, att);

    // output projection -> d_out (fp32)
    gemm_tf32_kernel<0><<<gemm_grid, gemm_block, GEMM_SMEM>>>(att, wo, bo, d_out,
                                                              M_ROWS, D_, D_, 1.0f);
}

// round 6
// speedup vs baseline: 1.8579x; 1.8579x over previous
#include <cuda_runtime.h>
#include <cuda_fp16.h>
#include <cstdint>

// Problem constants
#define B_ 4
#define S_ 2048
#define D_ 1024
#define H_ 16
#define DK_ 64
#define SCALE_ 0.125f   // 1/sqrt(64)

#define M_ROWS (B_ * S_)   // 8192

// ---------------- scratch (device globals; no allocation allowed) ----------
__device__ __half g_qin[B_ * S_ * D_];
__device__ __half g_kin[B_ * S_ * D_];
__device__ __half g_vin[B_ * S_ * D_];
__device__ __half g_wq[D_ * D_];     // transposed [N][K]
__device__ __half g_wk[D_ * D_];
__device__ __half g_wv[D_ * D_];
__device__ __half g_wo[D_ * D_];
__device__ __half g_q[B_ * H_ * S_ * DK_];    // [B,H,S,DK], pre-scaled
__device__ __half g_k[B_ * H_ * S_ * DK_];    // [B,H,S,DK]
__device__ __half g_vt[B_ * H_ * DK_ * S_];   // [B,H,DK,S]  (transposed V)
__device__ __half g_att[B_ * S_ * D_];        // [B,S,D]

// ---------------- helpers -----------------------------------------------------
__device__ __forceinline__ void mma_f16_16x8x16(
    float& c0, float& c1, float& c2, float& c3,
    uint32_t a0, uint32_t a1, uint32_t a2, uint32_t a3,
    uint32_t b0, uint32_t b1)
{
    asm volatile(
        "mma.sync.aligned.m16n8k16.row.col.f32.f16.f16.f32 "
        "{%0,%1,%2,%3}, {%4,%5,%6,%7}, {%8,%9}, {%0,%1,%2,%3};"
        : "+f"(c0), "+f"(c1), "+f"(c2), "+f"(c3)
        : "r"(a0), "r"(a1), "r"(a2), "r"(a3), "r"(b0), "r"(b1));
}

__device__ __forceinline__ void cp_async16(uint32_t smem_dst, const void* gsrc) {
    asm volatile("cp.async.cg.shared.global [%0], [%1], 16;"
                 :: "r"(smem_dst), "l"(gsrc));
}
__device__ __forceinline__ void cp_commit() {
    asm volatile("cp.async.commit_group;");
}
__device__ __forceinline__ void cp_wait0() {
    asm volatile("cp.async.wait_group 0;");
}
__device__ __forceinline__ uint32_t smaddr(const void* p) {
    return (uint32_t)__cvta_generic_to_shared(p);
}
__device__ __forceinline__ uint32_t h2u(__half2 h) {
    return *(uint32_t*)&h;
}

// ---------------- fp32 -> fp16 conversion (inputs) ----------------------------
__global__ __launch_bounds__(256)
void conv_h_kernel(const float4* __restrict__ in, uint2* __restrict__ out, int n4)
{
    const int i = blockIdx.x * 256 + threadIdx.x;
    if (i < n4) {
        float4 v = in[i];
        uint2 r;
        r.x = h2u(__floats2half2_rn(v.x, v.y));
        r.y = h2u(__floats2half2_rn(v.z, v.w));
        out[i] = r;
    }
}

// ---------------- fp32 [K][N] -> fp16 transposed [N][K] ------------------------
__global__ __launch_bounds__(256)
void convT_w_kernel(const float* __restrict__ W, __half* __restrict__ Wt)
{
    __shared__ float t[32][33];
    const int bn = blockIdx.x * 32;           // n base
    const int bk = blockIdx.y * 32;           // k base
    const int x = threadIdx.x;                // 0..31
    #pragma unroll
    for (int y = threadIdx.y; y < 32; y += 8)
        t[y][x] = W[(size_t)(bk + y) * D_ + bn + x];
    __syncthreads();
    #pragma unroll
    for (int y = threadIdx.y; y < 32; y += 8)
        Wt[(size_t)(bn + y) * D_ + bk + x] = __float2half(t[x][y]);
}

// ---------------- fp16 tensor-core GEMM (cp.async, 2-stage) --------------------
// C = A[M,K] @ Wt[N,K]^T + bias.  A, Wt fp16.
// MODE 0: C = float* row-major [M,N]
// MODE 1: C = half*  [B,H,S,DK], scaled by out_scale
// MODE 2: C = half*  [B,H,DK,S]  (transposed V layout)
#define GBM 128
#define GBN 128
#define GBKH 32                 // K per stage, in halves
#define G_STR 20                // row stride in uint32(half2) units: 16 + 4 pad
#define G_WORDS (128 * G_STR)   // 2560 words per tile

template <int MODE>
__global__ __launch_bounds__(256)
void gemm_f16_kernel(const __half* __restrict__ A, const __half* __restrict__ Wt,
                     const float* __restrict__ bias, void* __restrict__ Cout,
                     int M, int N, int K, float out_scale)
{
    __shared__ uint32_t As[2 * G_WORDS];
    __shared__ uint32_t Bs[2 * G_WORDS];

    const int tid  = threadIdx.x;
    const int warp = tid >> 5;
    const int lane = tid & 31;
    const int warpM = warp >> 2;            // 0..1
    const int warpN = warp & 3;             // 0..3
    const int lr = lane >> 2;
    const int lc = lane & 3;

    const int block_row = blockIdx.y;
    const int block_col = blockIdx.x;

    const __half* Ab = A  + (size_t)block_row * GBM * K;
    const __half* Wb = Wt + (size_t)block_col * GBN * K;

    float acc[4][4][4];
    #pragma unroll
    for (int mt = 0; mt < 4; mt++)
        #pragma unroll
        for (int nt = 0; nt < 4; nt++)
            #pragma unroll
            for (int r = 0; r < 4; r++) acc[mt][nt][r] = 0.f;

    // stage loader: A 128x32h = 512 chunks, B 128x32h = 512 chunks; 2+2/thread
    auto load_stage = [&](int k0, int buf) {
        uint32_t* Ad = As + buf * G_WORDS;
        uint32_t* Bd = Bs + buf * G_WORDS;
        #pragma unroll
        for (int u = 0; u < 2; u++) {
            const int flat = tid + u * 256;       // 0..511
            const int r = flat >> 2;              // 0..127
            const int c = (flat & 3);             // chunk within row (8 halves)
            cp_async16(smaddr(Ad + r * G_STR + c * 4), Ab + (size_t)r * K + k0 + c * 8);
            cp_async16(smaddr(Bd + r * G_STR + c * 4), Wb + (size_t)r * K + k0 + c * 8);
        }
    };

    const int NK = K / GBKH;   // 32
    load_stage(0, 0);
    cp_commit();

    for (int it = 0; it < NK; it++) {
        cp_wait0();
        __syncthreads();
        if (it + 1 < NK) { load_stage((it + 1) * GBKH, (it + 1) & 1); cp_commit(); }

        const uint32_t* As_s = As + (it & 1) * G_WORDS;
        const uint32_t* Bs_s = Bs + (it & 1) * G_WORDS;

        #pragma unroll
        for (int ch = 0; ch < 2; ch++) {        // two k16 chunks per stage
            const int ks2 = ch * 8;             // half2 offset
            uint32_t af[4][4];
            #pragma unroll
            for (int mt = 0; mt < 4; mt++) {
                const int m0 = warpM * 64 + mt * 16;
                af[mt][0] = As_s[(m0 + lr)     * G_STR + ks2 + lc];
                af[mt][1] = As_s[(m0 + 8 + lr) * G_STR + ks2 + lc];
                af[mt][2] = As_s[(m0 + lr)     * G_STR + ks2 + 4 + lc];
                af[mt][3] = As_s[(m0 + 8 + lr) * G_STR + ks2 + 4 + lc];
            }
            uint32_t bf[4][2];
            #pragma unroll
            for (int nt = 0; nt < 4; nt++) {
                const int n0 = warpN * 32 + nt * 8;
                bf[nt][0] = Bs_s[(n0 + lr) * G_STR + ks2 + lc];
                bf[nt][1] = Bs_s[(n0 + lr) * G_STR + ks2 + 4 + lc];
            }
            #pragma unroll
            for (int mt = 0; mt < 4; mt++)
                #pragma unroll
                for (int nt = 0; nt < 4; nt++)
                    mma_f16_16x8x16(acc[mt][nt][0], acc[mt][nt][1],
                                    acc[mt][nt][2], acc[mt][nt][3],
                                    af[mt][0], af[mt][1], af[mt][2], af[mt][3],
                                    bf[nt][0], bf[nt][1]);
        }
    }

    #pragma unroll
    for (int mt = 0; mt < 4; mt++) {
        #pragma unroll
        for (int nt = 0; nt < 4; nt++) {
            const int n = block_col * GBN + warpN * 32 + nt * 8 + lc * 2;
            #pragma unroll
            for (int half_ = 0; half_ < 2; half_++) {
                const int m = block_row * GBM + warpM * 64 + mt * 16 + lr + half_ * 8;
                const float v0 = acc[mt][nt][half_ * 2 + 0] + bias[n];
                const float v1 = acc[mt][nt][half_ * 2 + 1] + bias[n + 1];
                if (MODE == 0) {
                    float* C = (float*)Cout;
                    *(float2*)&C[(size_t)m * N + n] = make_float2(v0, v1);
                } else {
                    const int b  = m >> 11;
                    const int s  = m & 2047;
                    const int h  = n >> 6;
                    const int dk = n & 63;
                    __half* C = (__half*)Cout;
                    if (MODE == 1) {
                        *(__half2*)(C + (((size_t)(b * H_ + h)) * S_ + s) * DK_ + dk)
                            = __floats2half2_rn(v0 * out_scale, v1 * out_scale);
                    } else {   // MODE 2: V^T [B,H,DK,S]
                        C[(((size_t)(b * H_ + h)) * DK_ + dk)     * S_ + s] = __float2half(v0);
                        C[(((size_t)(b * H_ + h)) * DK_ + dk + 1) * S_ + s] = __float2half(v1);
                    }
                }
            }
        }
    }
}

// ---------------- fp16 tensor-core causal flash attention ----------------------
// 64 q-rows per block, 4 warps x 16 rows, 64-key double-buffered K / V^T tiles.
#define FSTR 36                  // 32 half2 + 4 pad
#define FTILE (64 * FSTR)        // 2304 words

__global__ __launch_bounds__(128)
void flash_attn_f16_kernel(const __half* __restrict__ q, const __half* __restrict__ k,
                           const __half* __restrict__ vt, __half* __restrict__ o)
{
    __shared__ uint32_t KsBuf[2][FTILE];
    __shared__ uint32_t VtBuf[2][FTILE];
    __shared__ uint32_t Pbuf[4][16 * FSTR];   // warp-private P

    const int qt  = gridDim.x - 1 - blockIdx.x;   // big blocks first
    const int bh  = blockIdx.y;
    const int tid = threadIdx.x;
    const int warp = tid >> 5;
    const int lane = tid & 31;
    const int lr = lane >> 2;
    const int lc = lane & 3;
    const int q0 = qt * 64;
    const int mb = warp * 16;
    uint32_t* Pw = Pbuf[warp];

    const __half* qb  = q  + (size_t)bh * S_ * DK_;
    const __half* kb  = k  + (size_t)bh * S_ * DK_;
    const __half* vtb = vt + (size_t)bh * DK_ * S_;

    // ---- stage Q tile (64x64h) into KsBuf[0]; 512 chunks, 4/thread ----
    #pragma unroll
    for (int i = 0; i < 4; i++) {
        const int flat = tid + 128 * i;
        const int row = flat >> 3;
        const int c = flat & 7;
        cp_async16(smaddr(&KsBuf[0][row * FSTR + c * 4]),
                   qb + (size_t)(q0 + row) * DK_ + c * 8);
    }
    cp_commit();
    cp_wait0();
    __syncthreads();

    uint32_t qf[4][4];
    #pragma unroll
    for (int i = 0; i < 4; i++) {
        qf[i][0] = KsBuf[0][(mb + lr)     * FSTR + 8 * i + lc];
        qf[i][1] = KsBuf[0][(mb + 8 + lr) * FSTR + 8 * i + lc];
        qf[i][2] = KsBuf[0][(mb + lr)     * FSTR + 8 * i + 4 + lc];
        qf[i][3] = KsBuf[0][(mb + 8 + lr) * FSTR + 8 * i + 4 + lc];
    }
    __syncthreads();   // done reading Q before K tile 0 overwrites

    float oacc[8][4];
    #pragma unroll
    for (int nt = 0; nt < 8; nt++)
        #pragma unroll
        for (int c = 0; c < 4; c++) oacc[nt][c] = 0.f;
    float mrow[2] = { -INFINITY, -INFINITY };
    float lrow[2] = { 0.f, 0.f };

    // K tile: [key][dk] rows; V^T tile: [dk][key] rows; both 64x64h
    auto load_k = [&](int k0, int buf) {
        #pragma unroll
        for (int i = 0; i < 4; i++) {
            const int flat = tid + 128 * i;
            const int row = flat >> 3;
            const int c = flat & 7;
            cp_async16(smaddr(&KsBuf[buf][row * FSTR + c * 4]),
                       kb + (size_t)(k0 + row) * DK_ + c * 8);
        }
    };
    auto load_v = [&](int k0, int buf) {
        #pragma unroll
        for (int i = 0; i < 4; i++) {
            const int flat = tid + 128 * i;
            const int row = flat >> 3;              // dk
            const int c = flat & 7;
            cp_async16(smaddr(&VtBuf[buf][row * FSTR + c * 4]),
                       vtb + (size_t)row * S_ + k0 + c * 8);
        }
    };

    const int NT = qt + 1;
    load_k(0, 0);
    load_v(0, 0);
    cp_commit();

    for (int kt = 0; kt < NT; kt++) {
        const int cur = kt & 1;
        cp_wait0();
        __syncthreads();
        if (kt + 1 < NT) {
            load_k((kt + 1) * 64, cur ^ 1);
            load_v((kt + 1) * 64, cur ^ 1);
            cp_commit();
        }
        const int k0 = kt * 64;
        const uint32_t* Ks = KsBuf[cur];
        const uint32_t* Vt = VtBuf[cur];

        // ---- S = Q @ K^T : 8 key-tiles x 4 k16-chunks ----
        float s[8][4];
        #pragma unroll
        for (int nt = 0; nt < 8; nt++) {
            s[nt][0] = s[nt][1] = s[nt][2] = s[nt][3] = 0.f;
            #pragma unroll
            for (int i = 0; i < 4; i++) {
                const uint32_t b0 = Ks[(nt * 8 + lr) * FSTR + 8 * i + lc];
                const uint32_t b1 = Ks[(nt * 8 + lr) * FSTR + 8 * i + 4 + lc];
                mma_f16_16x8x16(s[nt][0], s[nt][1], s[nt][2], s[nt][3],
                                qf[i][0], qf[i][1], qf[i][2], qf[i][3], b0, b1);
            }
        }

        // ---- causal mask (diagonal tile only) ----
        if (kt == qt) {
            const int r0 = q0 + mb + lr;
            const int r1 = r0 + 8;
            #pragma unroll
            for (int nt = 0; nt < 8; nt++) {
                const int cg = k0 + nt * 8 + 2 * lc;
                if (cg     > r0) s[nt][0] = -1e30f;
                if (cg + 1 > r0) s[nt][1] = -1e30f;
                if (cg     > r1) s[nt][2] = -1e30f;
                if (cg + 1 > r1) s[nt][3] = -1e30f;
            }
        }

        // ---- online softmax ----
        float m0 = -INFINITY, m1 = -INFINITY;
        #pragma unroll
        for (int nt = 0; nt < 8; nt++) {
            m0 = fmaxf(m0, fmaxf(s[nt][0], s[nt][1]));
            m1 = fmaxf(m1, fmaxf(s[nt][2], s[nt][3]));
        }
        m0 = fmaxf(m0, __shfl_xor_sync(0xffffffffu, m0, 1));
        m0 = fmaxf(m0, __shfl_xor_sync(0xffffffffu, m0, 2));
        m1 = fmaxf(m1, __shfl_xor_sync(0xffffffffu, m1, 1));
        m1 = fmaxf(m1, __shfl_xor_sync(0xffffffffu, m1, 2));

        const float mnew0 = fmaxf(mrow[0], m0);
        const float mnew1 = fmaxf(mrow[1], m1);
        const float alpha0 = __expf(mrow[0] - mnew0);
        const float alpha1 = __expf(mrow[1] - mnew1);
        float ls0 = 0.f, ls1 = 0.f;
        #pragma unroll
        for (int nt = 0; nt < 8; nt++) {
            s[nt][0] = __expf(s[nt][0] - mnew0);
            s[nt][1] = __expf(s[nt][1] - mnew0);
            s[nt][2] = __expf(s[nt][2] - mnew1);
            s[nt][3] = __expf(s[nt][3] - mnew1);
            ls0 += s[nt][0] + s[nt][1];
            ls1 += s[nt][2] + s[nt][3];
        }
        ls0 += __shfl_xor_sync(0xffffffffu, ls0, 1);
        ls0 += __shfl_xor_sync(0xffffffffu, ls0, 2);
        ls1 += __shfl_xor_sync(0xffffffffu, ls1, 1);
        ls1 += __shfl_xor_sync(0xffffffffu, ls1, 2);
        lrow[0] = lrow[0] * alpha0 + ls0;
        lrow[1] = lrow[1] * alpha1 + ls1;
        mrow[0] = mnew0;
        mrow[1] = mnew1;
        #pragma unroll
        for (int nt = 0; nt < 8; nt++) {
            oacc[nt][0] *= alpha0; oacc[nt][1] *= alpha0;
            oacc[nt][2] *= alpha1; oacc[nt][3] *= alpha1;
        }

        // ---- store P (fp16) into warp-private buffer ----
        #pragma unroll
        for (int nt = 0; nt < 8; nt++) {
            Pw[lr       * FSTR + nt * 4 + lc] = h2u(__floats2half2_rn(s[nt][0], s[nt][1]));
            Pw[(8 + lr) * FSTR + nt * 4 + lc] = h2u(__floats2half2_rn(s[nt][2], s[nt][3]));
        }
        __syncwarp();

        // ---- O += P @ V : 4 key-chunks x 8 dk-tiles ----
        #pragma unroll
        for (int i = 0; i < 4; i++) {
            uint32_t pf[4];
            pf[0] = Pw[lr       * FSTR + 8 * i + lc];
            pf[1] = Pw[(8 + lr) * FSTR + 8 * i + lc];
            pf[2] = Pw[lr       * FSTR + 8 * i + 4 + lc];
            pf[3] = Pw[(8 + lr) * FSTR + 8 * i + 4 + lc];
            #pragma unroll
            for (int nt = 0; nt < 8; nt++) {
                const uint32_t b0 = Vt[(nt * 8 + lr) * FSTR + 8 * i + lc];
                const uint32_t b1 = Vt[(nt * 8 + lr) * FSTR + 8 * i + 4 + lc];
                mma_f16_16x8x16(oacc[nt][0], oacc[nt][1], oacc[nt][2], oacc[nt][3],
                                pf[0], pf[1], pf[2], pf[3], b0, b1);
            }
        }
    }

    // ---- finalize & write fp16 to [B,S,D] ----
    const float inv0 = 1.f / lrow[0];
    const float inv1 = 1.f / lrow[1];
    const int b = bh >> 4;
    const int h = bh & 15;
    const int r0 = q0 + mb + lr;
    __half* ob0 = o + ((size_t)b * S_ + r0)     * D_ + h * DK_;
    __half* ob1 = o + ((size_t)b * S_ + r0 + 8) * D_ + h * DK_;
    #pragma unroll
    for (int nt = 0; nt < 8; nt++) {
        const int c = nt * 8 + 2 * lc;
        *(__half2*)(ob0 + c) = __floats2half2_rn(oacc[nt][0] * inv0, oacc[nt][1] * inv0);
        *(__half2*)(ob1 + c) = __floats2half2_rn(oacc[nt][2] * inv1, oacc[nt][3] * inv1);
    }
}

// ---------------- launch ------------------------------------------------------
extern "C" void kernel_launch(void* const* d_in, const int* in_sizes, int n_in,
                              void* d_out, int out_size)
{
    const float* Q  = (const float*)d_in[0];
    const float* K  = (const float*)d_in[1];
    const float* V  = (const float*)d_in[2];
    const float* Wq = (const float*)d_in[3];
    const float* bq = (const float*)d_in[4];
    const float* Wk = (const float*)d_in[5];
    const float* bk = (const float*)d_in[6];
    const float* Wv = (const float*)d_in[7];
    const float* bv = (const float*)d_in[8];
    const float* Wo = (const float*)d_in[9];
    const float* bo = (const float*)d_in[10];
    // d_in[11] = mask (causal, known statically; ignored)

    __half *qin, *kin, *vin, *wq, *wk, *wv, *wo, *q, *k, *vt, *att;
    cudaGetSymbolAddress((void**)&qin, g_qin);
    cudaGetSymbolAddress((void**)&kin, g_kin);
    cudaGetSymbolAddress((void**)&vin, g_vin);
    cudaGetSymbolAddress((void**)&wq,  g_wq);
    cudaGetSymbolAddress((void**)&wk,  g_wk);
    cudaGetSymbolAddress((void**)&wv,  g_wv);
    cudaGetSymbolAddress((void**)&wo,  g_wo);
    cudaGetSymbolAddress((void**)&q,   g_q);
    cudaGetSymbolAddress((void**)&k,   g_k);
    cudaGetSymbolAddress((void**)&vt,  g_vt);
    cudaGetSymbolAddress((void**)&att, g_att);

    // fp32 -> fp16 conversion (inputs) and transpose-conversion (weights)
    const int n4_in = (B_ * S_ * D_) / 4;
    conv_h_kernel<<<(n4_in + 255) / 256, 256>>>((const float4*)Q, (uint2*)qin, n4_in);
    conv_h_kernel<<<(n4_in + 255) / 256, 256>>>((const float4*)K, (uint2*)kin, n4_in);
    conv_h_kernel<<<(n4_in + 255) / 256, 256>>>((const float4*)V, (uint2*)vin, n4_in);
    const dim3 wt_grid(D_ / 32, D_ / 32);
    const dim3 wt_block(32, 8);
    convT_w_kernel<<<wt_grid, wt_block>>>(Wq, wq);
    convT_w_kernel<<<wt_grid, wt_block>>>(Wk, wk);
    convT_w_kernel<<<wt_grid, wt_block>>>(Wv, wv);
    convT_w_kernel<<<wt_grid, wt_block>>>(Wo, wo);

    const dim3 gemm_grid(D_ / GBN, M_ROWS / GBM);   // (8, 64)
    const dim3 gemm_block(256);

    // QKV projections; Q pre-scaled; V written transposed
    gemm_f16_kernel<1><<<gemm_grid, gemm_block>>>(qin, wq, bq, q,  M_ROWS, D_, D_, SCALE_);
    gemm_f16_kernel<1><<<gemm_grid, gemm_block>>>(kin, wk, bk, k,  M_ROWS, D_, D_, 1.0f);
    gemm_f16_kernel<2><<<gemm_grid, gemm_block>>>(vin, wv, bv, vt, M_ROWS, D_, D_, 1.0f);

    // causal flash attention -> fp16 [B,S,D]
    const dim3 fa_grid(S_ / 64, B_ * H_);           // (32, 64)
    flash_attn_f16_kernel<<<fa_grid, 128>>>(q, k, vt, att);

    // output projection -> d_out (fp32)
    gemm_f16_kernel<0><<<gemm_grid, gemm_block>>>(att, wo, bo, d_out,
                                                  M_ROWS, D_, D_, 1.0f);
}

// round 8
// speedup vs baseline: 2.1244x; 1.1434x over previous
#include <cuda_runtime.h>
#include <cuda_fp16.h>
#include <cstdint>

// Problem constants
#define B_ 4
#define S_ 2048
#define D_ 1024
#define H_ 16
#define DK_ 64
#define QSCALE_ 0.1803368801111137f   // (1/sqrt(64)) * log2(e)

#define M_ROWS (B_ * S_)   // 8192

// ---------------- scratch (device globals; no allocation allowed) ----------
__device__ __half g_qin[B_ * S_ * D_];
__device__ __half g_kin[B_ * S_ * D_];
__device__ __half g_vin[B_ * S_ * D_];
__device__ __half g_wq[D_ * D_];     // transposed [N][K]
__device__ __half g_wk[D_ * D_];
__device__ __half g_wv[D_ * D_];
__device__ __half g_wo[D_ * D_];
__device__ __half g_q[B_ * H_ * S_ * DK_];    // [B,H,S,DK], pre-scaled by QSCALE_
__device__ __half g_k[B_ * H_ * S_ * DK_];    // [B,H,S,DK]
__device__ __half g_vt[B_ * H_ * DK_ * S_];   // [B,H,DK,S]  (transposed V)
__device__ __half g_att[B_ * S_ * D_];        // [B,S,D]

// ---------------- helpers -----------------------------------------------------
__device__ __forceinline__ void mma_f16_16x8x16(
    float& c0, float& c1, float& c2, float& c3,
    uint32_t a0, uint32_t a1, uint32_t a2, uint32_t a3,
    uint32_t b0, uint32_t b1)
{
    asm volatile(
        "mma.sync.aligned.m16n8k16.row.col.f32.f16.f16.f32 "
        "{%0,%1,%2,%3}, {%4,%5,%6,%7}, {%8,%9}, {%0,%1,%2,%3};"
        : "+f"(c0), "+f"(c1), "+f"(c2), "+f"(c3)
        : "r"(a0), "r"(a1), "r"(a2), "r"(a3), "r"(b0), "r"(b1));
}

__device__ __forceinline__ void cp_async16(uint32_t smem_dst, const void* gsrc) {
    asm volatile("cp.async.cg.shared.global [%0], [%1], 16;"
                 :: "r"(smem_dst), "l"(gsrc));
}
__device__ __forceinline__ void cp_commit() {
    asm volatile("cp.async.commit_group;");
}
__device__ __forceinline__ void cp_wait0() {
    asm volatile("cp.async.wait_group 0;");
}
__device__ __forceinline__ uint32_t smaddr(const void* p) {
    return (uint32_t)__cvta_generic_to_shared(p);
}
__device__ __forceinline__ uint32_t h2u(__half2 h) {
    return *(uint32_t*)&h;
}
__device__ __forceinline__ float fexp2(float x) {
    float y;
    asm("ex2.approx.f32 %0, %1;" : "=f"(y) : "f"(x));
    return y;
}

// ---------------- fused fp32 -> fp16 conversion (Q,K,V inputs) -----------------
__global__ __launch_bounds__(256)
void conv_h3_kernel(const float4* __restrict__ a, const float4* __restrict__ b,
                    const float4* __restrict__ c,
                    uint2* __restrict__ oa, uint2* __restrict__ ob,
                    uint2* __restrict__ oc, int n4)
{
    const int i = blockIdx.x * 256 + threadIdx.x;
    if (i >= n4) return;
    const float4* in = blockIdx.y == 0 ? a : (blockIdx.y == 1 ? b : c);
    uint2* out       = blockIdx.y == 0 ? oa : (blockIdx.y == 1 ? ob : oc);
    float4 v = in[i];
    uint2 r;
    r.x = h2u(__floats2half2_rn(v.x, v.y));
    r.y = h2u(__floats2half2_rn(v.z, v.w));
    out[i] = r;
}

// ---------------- fused fp32 [K][N] -> fp16 transposed [N][K] (4 weights) ------
__global__ __launch_bounds__(256)
void convT_w4_kernel(const float* __restrict__ W0, const float* __restrict__ W1,
                     const float* __restrict__ W2, const float* __restrict__ W3,
                     __half* __restrict__ T0, __half* __restrict__ T1,
                     __half* __restrict__ T2, __half* __restrict__ T3)
{
    __shared__ float t[32][33];
    const float* W = blockIdx.z == 0 ? W0 : (blockIdx.z == 1 ? W1 :
                     (blockIdx.z == 2 ? W2 : W3));
    __half* Wt     = blockIdx.z == 0 ? T0 : (blockIdx.z == 1 ? T1 :
                     (blockIdx.z == 2 ? T2 : T3));
    const int bn = blockIdx.x * 32;
    const int bk = blockIdx.y * 32;
    const int x = threadIdx.x;
    #pragma unroll
    for (int y = threadIdx.y; y < 32; y += 8)
        t[y][x] = W[(size_t)(bk + y) * D_ + bn + x];
    __syncthreads();
    #pragma unroll
    for (int y = threadIdx.y; y < 32; y += 8)
        Wt[(size_t)(bn + y) * D_ + bk + x] = __float2half(t[x][y]);
}

// ---------------- fp16 tensor-core GEMM core (cp.async, 2-stage) ---------------
// C = A[M,K] @ Wt[N,K]^T + bias.
// mode 0: float* row-major [M,N]; mode 1: half* [B,H,S,DK]*out_scale;
// mode 2: half* [B,H,DK,S].
#define GBKH 32                 // K per stage, in halves
#define G_STR 20                // row stride in uint32(half2) units
#define G_WORDS (128 * G_STR)

__device__ __forceinline__
void gemm_f16_body(const __half* __restrict__ A, const __half* __restrict__ Wt,
                   const float* __restrict__ bias, void* __restrict__ Cout,
                   int mode, float out_scale,
                   uint32_t* As, uint32_t* Bs)
{
    const int K = D_, N = D_;
    const int tid  = threadIdx.x;
    const int warp = tid >> 5;
    const int lane = tid & 31;
    const int warpM = warp >> 2;
    const int warpN = warp & 3;
    const int lr = lane >> 2;
    const int lc = lane & 3;

    const int block_row = blockIdx.y;
    const int block_col = blockIdx.x;

    const __half* Ab = A  + (size_t)block_row * 128 * K;
    const __half* Wb = Wt + (size_t)block_col * 128 * K;

    float acc[4][4][4];
    #pragma unroll
    for (int mt = 0; mt < 4; mt++)
        #pragma unroll
        for (int nt = 0; nt < 4; nt++)
            #pragma unroll
            for (int r = 0; r < 4; r++) acc[mt][nt][r] = 0.f;

    auto load_stage = [&](int k0, int buf) {
        uint32_t* Ad = As + buf * G_WORDS;
        uint32_t* Bd = Bs + buf * G_WORDS;
        #pragma unroll
        for (int u = 0; u < 2; u++) {
            const int flat = tid + u * 256;
            const int r = flat >> 2;
            const int c = (flat & 3);
            cp_async16(smaddr(Ad + r * G_STR + c * 4), Ab + (size_t)r * K + k0 + c * 8);
            cp_async16(smaddr(Bd + r * G_STR + c * 4), Wb + (size_t)r * K + k0 + c * 8);
        }
    };

    const int NK = K / GBKH;
    load_stage(0, 0);
    cp_commit();

    for (int it = 0; it < NK; it++) {
        cp_wait0();
        __syncthreads();
        if (it + 1 < NK) { load_stage((it + 1) * GBKH, (it + 1) & 1); cp_commit(); }

        const uint32_t* As_s = As + (it & 1) * G_WORDS;
        const uint32_t* Bs_s = Bs + (it & 1) * G_WORDS;

        #pragma unroll
        for (int ch = 0; ch < 2; ch++) {
            const int ks2 = ch * 8;
            uint32_t af[4][4];
            #pragma unroll
            for (int mt = 0; mt < 4; mt++) {
                const int m0 = warpM * 64 + mt * 16;
                af[mt][0] = As_s[(m0 + lr)     * G_STR + ks2 + lc];
                af[mt][1] = As_s[(m0 + 8 + lr) * G_STR + ks2 + lc];
                af[mt][2] = As_s[(m0 + lr)     * G_STR + ks2 + 4 + lc];
                af[mt][3] = As_s[(m0 + 8 + lr) * G_STR + ks2 + 4 + lc];
            }
            uint32_t bf[4][2];
            #pragma unroll
            for (int nt = 0; nt < 4; nt++) {
                const int n0 = warpN * 32 + nt * 8;
                bf[nt][0] = Bs_s[(n0 + lr) * G_STR + ks2 + lc];
                bf[nt][1] = Bs_s[(n0 + lr) * G_STR + ks2 + 4 + lc];
            }
            #pragma unroll
            for (int mt = 0; mt < 4; mt++)
                #pragma unroll
                for (int nt = 0; nt < 4; nt++)
                    mma_f16_16x8x16(acc[mt][nt][0], acc[mt][nt][1],
                                    acc[mt][nt][2], acc[mt][nt][3],
                                    af[mt][0], af[mt][1], af[mt][2], af[mt][3],
                                    bf[nt][0], bf[nt][1]);
        }
    }

    #pragma unroll
    for (int mt = 0; mt < 4; mt++) {
        #pragma unroll
        for (int nt = 0; nt < 4; nt++) {
            const int n = block_col * 128 + warpN * 32 + nt * 8 + lc * 2;
            #pragma unroll
            for (int half_ = 0; half_ < 2; half_++) {
                const int m = block_row * 128 + warpM * 64 + mt * 16 + lr + half_ * 8;
                const float v0 = acc[mt][nt][half_ * 2 + 0] + bias[n];
                const float v1 = acc[mt][nt][half_ * 2 + 1] + bias[n + 1];
                if (mode == 0) {
                    float* C = (float*)Cout;
                    *(float2*)&C[(size_t)m * N + n] = make_float2(v0, v1);
                } else {
                    const int b  = m >> 11;
                    const int s  = m & 2047;
                    const int h  = n >> 6;
                    const int dk = n & 63;
                    __half* C = (__half*)Cout;
                    if (mode == 1) {
                        *(__half2*)(C + (((size_t)(b * H_ + h)) * S_ + s) * DK_ + dk)
                            = __floats2half2_rn(v0 * out_scale, v1 * out_scale);
                    } else {
                        C[(((size_t)(b * H_ + h)) * DK_ + dk)     * S_ + s] = __float2half(v0);
                        C[(((size_t)(b * H_ + h)) * DK_ + dk + 1) * S_ + s] = __float2half(v1);
                    }
                }
            }
        }
    }
}

// fused QKV projections (grid.z selects tensor)
__global__ __launch_bounds__(256)
void gemm_qkv_kernel(const __half* __restrict__ qin, const __half* __restrict__ kin,
                     const __half* __restrict__ vin,
                     const __half* __restrict__ wq, const __half* __restrict__ wk,
                     const __half* __restrict__ wv,
                     const float* __restrict__ bq, const float* __restrict__ bk,
                     const float* __restrict__ bv,
                     __half* __restrict__ q, __half* __restrict__ k,
                     __half* __restrict__ vt)
{
    __shared__ uint32_t As[2 * G_WORDS];
    __shared__ uint32_t Bs[2 * G_WORDS];
    const int z = blockIdx.z;
    if (z == 0)      gemm_f16_body(qin, wq, bq, q,  1, QSCALE_, As, Bs);
    else if (z == 1) gemm_f16_body(kin, wk, bk, k,  1, 1.0f,    As, Bs);
    else             gemm_f16_body(vin, wv, bv, vt, 2, 1.0f,    As, Bs);
}

// output projection
__global__ __launch_bounds__(256)
void gemm_out_kernel(const __half* __restrict__ att, const __half* __restrict__ wo,
                     const float* __restrict__ bo, float* __restrict__ out)
{
    __shared__ uint32_t As[2 * G_WORDS];
    __shared__ uint32_t Bs[2 * G_WORDS];
    gemm_f16_body(att, wo, bo, out, 0, 1.0f, As, Bs);
}

// ---------------- fp16 tensor-core causal flash attention ----------------------
// 64 q-rows per block, 4 warps x 16 rows, double-buffered K / V^T tiles,
// P kept entirely in registers (QK C-fragment == PV A-fragment).
#define FSTR 36                  // 32 half2 + 4 pad
#define FTILE (64 * FSTR)

__global__ __launch_bounds__(128)
void flash_attn_f16_kernel(const __half* __restrict__ q, const __half* __restrict__ k,
                           const __half* __restrict__ vt, __half* __restrict__ o)
{
    __shared__ uint32_t KsBuf[2][FTILE];
    __shared__ uint32_t VtBuf[2][FTILE];

    const int qt  = gridDim.x - 1 - blockIdx.x;   // big blocks first
    const int bh  = blockIdx.y;
    const int tid = threadIdx.x;
    const int warp = tid >> 5;
    const int lane = tid & 31;
    const int lr = lane >> 2;
    const int lc = lane & 3;
    const int q0 = qt * 64;
    const int mb = warp * 16;

    const __half* qb  = q  + (size_t)bh * S_ * DK_;
    const __half* kb  = k  + (size_t)bh * S_ * DK_;
    const __half* vtb = vt + (size_t)bh * DK_ * S_;

    // stage Q tile (64x64h) into KsBuf[0]
    #pragma unroll
    for (int i = 0; i < 4; i++) {
        const int flat = tid + 128 * i;
        const int row = flat >> 3;
        const int c = flat & 7;
        cp_async16(smaddr(&KsBuf[0][row * FSTR + c * 4]),
                   qb + (size_t)(q0 + row) * DK_ + c * 8);
    }
    cp_commit();
    cp_wait0();
    __syncthreads();

    uint32_t qf[4][4];
    #pragma unroll
    for (int i = 0; i < 4; i++) {
        qf[i][0] = KsBuf[0][(mb + lr)     * FSTR + 8 * i + lc];
        qf[i][1] = KsBuf[0][(mb + 8 + lr) * FSTR + 8 * i + lc];
        qf[i][2] = KsBuf[0][(mb + lr)     * FSTR + 8 * i + 4 + lc];
        qf[i][3] = KsBuf[0][(mb + 8 + lr) * FSTR + 8 * i + 4 + lc];
    }
    __syncthreads();

    float oacc[8][4];
    #pragma unroll
    for (int nt = 0; nt < 8; nt++)
        #pragma unroll
        for (int c = 0; c < 4; c++) oacc[nt][c] = 0.f;
    float mrow[2] = { -INFINITY, -INFINITY };
    float lrow[2] = { 0.f, 0.f };

    auto load_k = [&](int k0, int buf) {
        #pragma unroll
        for (int i = 0; i < 4; i++) {
            const int flat = tid + 128 * i;
            const int row = flat >> 3;
            const int c = flat & 7;
            cp_async16(smaddr(&KsBuf[buf][row * FSTR + c * 4]),
                       kb + (size_t)(k0 + row) * DK_ + c * 8);
        }
    };
    auto load_v = [&](int k0, int buf) {
        #pragma unroll
        for (int i = 0; i < 4; i++) {
            const int flat = tid + 128 * i;
            const int row = flat >> 3;
            const int c = flat & 7;
            cp_async16(smaddr(&VtBuf[buf][row * FSTR + c * 4]),
                       vtb + (size_t)row * S_ + k0 + c * 8);
        }
    };

    const int NT = qt + 1;
    load_k(0, 0);
    load_v(0, 0);
    cp_commit();

    for (int kt = 0; kt < NT; kt++) {
        const int cur = kt & 1;
        cp_wait0();
        __syncthreads();
        if (kt + 1 < NT) {
            load_k((kt + 1) * 64, cur ^ 1);
            load_v((kt + 1) * 64, cur ^ 1);
            cp_commit();
        }
        const int k0 = kt * 64;
        const uint32_t* Ks = KsBuf[cur];
        const uint32_t* Vt = VtBuf[cur];

        // ---- S = Q @ K^T (scores in log2 domain; Q pre-scaled) ----
        float s[8][4];
        #pragma unroll
        for (int nt = 0; nt < 8; nt++) {
            s[nt][0] = s[nt][1] = s[nt][2] = s[nt][3] = 0.f;
            #pragma unroll
            for (int i = 0; i < 4; i++) {
                const uint32_t b0 = Ks[(nt * 8 + lr) * FSTR + 8 * i + lc];
                const uint32_t b1 = Ks[(nt * 8 + lr) * FSTR + 8 * i + 4 + lc];
                mma_f16_16x8x16(s[nt][0], s[nt][1], s[nt][2], s[nt][3],
                                qf[i][0], qf[i][1], qf[i][2], qf[i][3], b0, b1);
            }
        }

        // ---- causal mask (diagonal tile only) ----
        if (kt == qt) {
            const int r0 = q0 + mb + lr;
            const int r1 = r0 + 8;
            #pragma unroll
            for (int nt = 0; nt < 8; nt++) {
                const int cg = k0 + nt * 8 + 2 * lc;
                if (cg     > r0) s[nt][0] = -1e30f;
                if (cg + 1 > r0) s[nt][1] = -1e30f;
                if (cg     > r1) s[nt][2] = -1e30f;
                if (cg + 1 > r1) s[nt][3] = -1e30f;
            }
        }

        // ---- online softmax (base-2) ----
        float m0 = -INFINITY, m1 = -INFINITY;
        #pragma unroll
        for (int nt = 0; nt < 8; nt++) {
            m0 = fmaxf(m0, fmaxf(s[nt][0], s[nt][1]));
            m1 = fmaxf(m1, fmaxf(s[nt][2], s[nt][3]));
        }
        m0 = fmaxf(m0, __shfl_xor_sync(0xffffffffu, m0, 1));
        m0 = fmaxf(m0, __shfl_xor_sync(0xffffffffu, m0, 2));
        m1 = fmaxf(m1, __shfl_xor_sync(0xffffffffu, m1, 1));
        m1 = fmaxf(m1, __shfl_xor_sync(0xffffffffu, m1, 2));

        const float mnew0 = fmaxf(mrow[0], m0);
        const float mnew1 = fmaxf(mrow[1], m1);
        const float alpha0 = fexp2(mrow[0] - mnew0);
        const float alpha1 = fexp2(mrow[1] - mnew1);
        float ls0 = 0.f, ls1 = 0.f;
        #pragma unroll
        for (int nt = 0; nt < 8; nt++) {
            s[nt][0] = fexp2(s[nt][0] - mnew0);
            s[nt][1] = fexp2(s[nt][1] - mnew0);
            s[nt][2] = fexp2(s[nt][2] - mnew1);
            s[nt][3] = fexp2(s[nt][3] - mnew1);
            ls0 += s[nt][0] + s[nt][1];
            ls1 += s[nt][2] + s[nt][3];
        }
        ls0 += __shfl_xor_sync(0xffffffffu, ls0, 1);
        ls0 += __shfl_xor_sync(0xffffffffu, ls0, 2);
        ls1 += __shfl_xor_sync(0xffffffffu, ls1, 1);
        ls1 += __shfl_xor_sync(0xffffffffu, ls1, 2);
        lrow[0] = lrow[0] * alpha0 + ls0;
        lrow[1] = lrow[1] * alpha1 + ls1;
        mrow[0] = mnew0;
        mrow[1] = mnew1;
        #pragma unroll
        for (int nt = 0; nt < 8; nt++) {
            oacc[nt][0] *= alpha0; oacc[nt][1] *= alpha0;
            oacc[nt][2] *= alpha1; oacc[nt][3] *= alpha1;
        }

        // ---- O += P @ V : P packed directly from registers ----
        #pragma unroll
        for (int i = 0; i < 4; i++) {
            const uint32_t pf0 = h2u(__floats2half2_rn(s[2 * i][0],     s[2 * i][1]));
            const uint32_t pf1 = h2u(__floats2half2_rn(s[2 * i][2],     s[2 * i][3]));
            const uint32_t pf2 = h2u(__floats2half2_rn(s[2 * i + 1][0], s[2 * i + 1][1]));
            const uint32_t pf3 = h2u(__floats2half2_rn(s[2 * i + 1][2], s[2 * i + 1][3]));
            #pragma unroll
            for (int nt = 0; nt < 8; nt++) {
                const uint32_t b0 = Vt[(nt * 8 + lr) * FSTR + 8 * i + lc];
                const uint32_t b1 = Vt[(nt * 8 + lr) * FSTR + 8 * i + 4 + lc];
                mma_f16_16x8x16(oacc[nt][0], oacc[nt][1], oacc[nt][2], oacc[nt][3],
                                pf0, pf1, pf2, pf3, b0, b1);
            }
        }
    }

    // ---- finalize & write fp16 to [B,S,D] ----
    const float inv0 = 1.f / lrow[0];
    const float inv1 = 1.f / lrow[1];
    const int b = bh >> 4;
    const int h = bh & 15;
    const int r0 = q0 + mb + lr;
    __half* ob0 = o + ((size_t)b * S_ + r0)     * D_ + h * DK_;
    __half* ob1 = o + ((size_t)b * S_ + r0 + 8) * D_ + h * DK_;
    #pragma unroll
    for (int nt = 0; nt < 8; nt++) {
        const int c = nt * 8 + 2 * lc;
        *(__half2*)(ob0 + c) = __floats2half2_rn(oacc[nt][0] * inv0, oacc[nt][1] * inv0);
        *(__half2*)(ob1 + c) = __floats2half2_rn(oacc[nt][2] * inv1, oacc[nt][3] * inv1);
    }
}

// ---------------- launch ------------------------------------------------------
extern "C" void kernel_launch(void* const* d_in, const int* in_sizes, int n_in,
                              void* d_out, int out_size)
{
    const float* Q  = (const float*)d_in[0];
    const float* K  = (const float*)d_in[1];
    const float* V  = (const float*)d_in[2];
    const float* Wq = (const float*)d_in[3];
    const float* bq = (const float*)d_in[4];
    const float* Wk = (const float*)d_in[5];
    const float* bk = (const float*)d_in[6];
    const float* Wv = (const float*)d_in[7];
    const float* bv = (const float*)d_in[8];
    const float* Wo = (const float*)d_in[9];
    const float* bo = (const float*)d_in[10];
    // d_in[11] = mask (causal, known statically; ignored)

    __half *qin, *kin, *vin, *wq, *wk, *wv, *wo, *q, *k, *vt, *att;
    cudaGetSymbolAddress((void**)&qin, g_qin);
    cudaGetSymbolAddress((void**)&kin, g_kin);
    cudaGetSymbolAddress((void**)&vin, g_vin);
    cudaGetSymbolAddress((void**)&wq,  g_wq);
    cudaGetSymbolAddress((void**)&wk,  g_wk);
    cudaGetSymbolAddress((void**)&wv,  g_wv);
    cudaGetSymbolAddress((void**)&wo,  g_wo);
    cudaGetSymbolAddress((void**)&q,   g_q);
    cudaGetSymbolAddress((void**)&k,   g_k);
    cudaGetSymbolAddress((void**)&vt,  g_vt);
    cudaGetSymbolAddress((void**)&att, g_att);

    // fused conversions
    const int n4_in = (B_ * S_ * D_) / 4;
    const dim3 c3_grid((n4_in + 255) / 256, 3);
    conv_h3_kernel<<<c3_grid, 256>>>((const float4*)Q, (const float4*)K,
                                     (const float4*)V, (uint2*)qin, (uint2*)kin,
                                     (uint2*)vin, n4_in);
    const dim3 wt_grid(D_ / 32, D_ / 32, 4);
    const dim3 wt_block(32, 8);
    convT_w4_kernel<<<wt_grid, wt_block>>>(Wq, Wk, Wv, Wo, wq, wk, wv, wo);

    // fused QKV projections (Q pre-scaled into log2 domain; V transposed)
    const dim3 qkv_grid(D_ / 128, M_ROWS / 128, 3);   // (8, 64, 3)
    gemm_qkv_kernel<<<qkv_grid, 256>>>(qin, kin, vin, wq, wk, wv,
                                       bq, bk, bv, q, k, vt);

    // causal flash attention -> fp16 [B,S,D]
    const dim3 fa_grid(S_ / 64, B_ * H_);             // (32, 64)
    flash_attn_f16_kernel<<<fa_grid, 128>>>(q, k, vt, att);

    // output projection -> d_out (fp32)
    const dim3 out_grid(D_ / 128, M_ROWS / 128);
    gemm_out_kernel<<<out_grid, 256>>>(att, wo, bo, (float*)d_out);
}

// round 9
// speedup vs baseline: 2.4488x; 1.1527x over previous
#include <cuda_runtime.h>
#include <cuda_fp16.h>
#include <cstdint>

// Problem constants
#define B_ 4
#define S_ 2048
#define D_ 1024
#define H_ 16
#define DK_ 64
#define QSCALE_ 0.1803368801111137f   // (1/sqrt(64)) * log2(e)

#define M_ROWS (B_ * S_)   // 8192

// ---------------- scratch (device globals; no allocation allowed) ----------
__device__ __half g_qin[B_ * S_ * D_];
__device__ __half g_kin[B_ * S_ * D_];
__device__ __half g_vin[B_ * S_ * D_];
__device__ __half g_wq[D_ * D_];     // transposed [N][K]
__device__ __half g_wk[D_ * D_];
__device__ __half g_wv[D_ * D_];
__device__ __half g_wo[D_ * D_];
__device__ __half g_q[B_ * H_ * S_ * DK_];    // [B,H,S,DK], pre-scaled by QSCALE_
__device__ __half g_k[B_ * H_ * S_ * DK_];    // [B,H,S,DK]
__device__ __half g_vt[B_ * H_ * DK_ * S_];   // [B,H,DK,S]  (transposed V)
__device__ __half g_att[B_ * S_ * D_];        // [B,S,D]

// ---------------- helpers -----------------------------------------------------
__device__ __forceinline__ void mma_f16_16x8x16(
    float& c0, float& c1, float& c2, float& c3,
    uint32_t a0, uint32_t a1, uint32_t a2, uint32_t a3,
    uint32_t b0, uint32_t b1)
{
    asm volatile(
        "mma.sync.aligned.m16n8k16.row.col.f32.f16.f16.f32 "
        "{%0,%1,%2,%3}, {%4,%5,%6,%7}, {%8,%9}, {%0,%1,%2,%3};"
        : "+f"(c0), "+f"(c1), "+f"(c2), "+f"(c3)
        : "r"(a0), "r"(a1), "r"(a2), "r"(a3), "r"(b0), "r"(b1));
}

__device__ __forceinline__ void ldsm_x4(uint32_t& r0, uint32_t& r1,
                                        uint32_t& r2, uint32_t& r3, uint32_t a)
{
    asm volatile("ldmatrix.sync.aligned.m8n8.x4.shared.b16 {%0,%1,%2,%3}, [%4];"
                 : "=r"(r0), "=r"(r1), "=r"(r2), "=r"(r3) : "r"(a));
}

__device__ __forceinline__ void cp_async16(uint32_t smem_dst, const void* gsrc) {
    asm volatile("cp.async.cg.shared.global [%0], [%1], 16;"
                 :: "r"(smem_dst), "l"(gsrc));
}
__device__ __forceinline__ void cp_commit() {
    asm volatile("cp.async.commit_group;");
}
__device__ __forceinline__ void cp_wait0() {
    asm volatile("cp.async.wait_group 0;");
}
__device__ __forceinline__ uint32_t smaddr(const void* p) {
    return (uint32_t)__cvta_generic_to_shared(p);
}
__device__ __forceinline__ uint32_t h2u(__half2 h) {
    return *(uint32_t*)&h;
}
__device__ __forceinline__ float fexp2(float x) {
    float y;
    asm("ex2.approx.f32 %0, %1;" : "=f"(y) : "f"(x));
    return y;
}

// ---------------- fused fp32 -> fp16 conversion (Q,K,V inputs) -----------------
__global__ __launch_bounds__(256)
void conv_h3_kernel(const float4* __restrict__ a, const float4* __restrict__ b,
                    const float4* __restrict__ c,
                    uint2* __restrict__ oa, uint2* __restrict__ ob,
                    uint2* __restrict__ oc, int n4)
{
    const int i = blockIdx.x * 256 + threadIdx.x;
    if (i >= n4) return;
    const float4* in = blockIdx.y == 0 ? a : (blockIdx.y == 1 ? b : c);
    uint2* out       = blockIdx.y == 0 ? oa : (blockIdx.y == 1 ? ob : oc);
    float4 v = in[i];
    uint2 r;
    r.x = h2u(__floats2half2_rn(v.x, v.y));
    r.y = h2u(__floats2half2_rn(v.z, v.w));
    out[i] = r;
}

// ---------------- fused fp32 [K][N] -> fp16 transposed [N][K] (4 weights) ------
__global__ __launch_bounds__(256)
void convT_w4_kernel(const float* __restrict__ W0, const float* __restrict__ W1,
                     const float* __restrict__ W2, const float* __restrict__ W3,
                     __half* __restrict__ T0, __half* __restrict__ T1,
                     __half* __restrict__ T2, __half* __restrict__ T3)
{
    __shared__ float t[32][33];
    const float* W = blockIdx.z == 0 ? W0 : (blockIdx.z == 1 ? W1 :
                     (blockIdx.z == 2 ? W2 : W3));
    __half* Wt     = blockIdx.z == 0 ? T0 : (blockIdx.z == 1 ? T1 :
                     (blockIdx.z == 2 ? T2 : T3));
    const int bn = blockIdx.x * 32;
    const int bk = blockIdx.y * 32;
    const int x = threadIdx.x;
    #pragma unroll
    for (int y = threadIdx.y; y < 32; y += 8)
        t[y][x] = W[(size_t)(bk + y) * D_ + bn + x];
    __syncthreads();
    #pragma unroll
    for (int y = threadIdx.y; y < 32; y += 8)
        Wt[(size_t)(bn + y) * D_ + bk + x] = __float2half(t[x][y]);
}

// ---------------- fp16 tensor-core GEMM core (cp.async + ldmatrix) -------------
// C = A[M,K] @ Wt[N,K]^T + bias.
// mode 0: float* row-major [M,N]; mode 1: half* [B,H,S,DK]*out_scale;
// mode 2: half* [B,H,DK,S].
#define GBKH 32                 // K per stage, in halves
#define G_STR 20                // row stride in uint32(half2) units
#define G_WORDS (128 * G_WORDS_DUMMY)
#undef G_WORDS
#define G_WORDS (128 * G_STR)

__device__ __forceinline__
void gemm_f16_body(const __half* __restrict__ A, const __half* __restrict__ Wt,
                   const float* __restrict__ bias, void* __restrict__ Cout,
                   int mode, float out_scale,
                   uint32_t* As, uint32_t* Bs)
{
    const int K = D_, N = D_;
    const int tid  = threadIdx.x;
    const int warp = tid >> 5;
    const int lane = tid & 31;
    const int warpM = warp >> 2;
    const int warpN = warp & 3;
    const int lr = lane >> 2;
    const int lc = lane & 3;

    // ldmatrix lane->address selectors
    const int arow = ((lane >> 3) & 1) * 8 + (lane & 7);   // A: m8 select in bit3
    const int acol = ((lane >> 4) & 1) * 4;                // A: k-chunk in bit4
    const int brow = ((lane >> 4) & 1) * 8 + (lane & 7);   // B: n8 select in bit4
    const int bcol = ((lane >> 3) & 1) * 4;                // B: k-chunk in bit3

    const int block_row = blockIdx.y;
    const int block_col = blockIdx.x;

    const __half* Ab = A  + (size_t)block_row * 128 * K;
    const __half* Wb = Wt + (size_t)block_col * 128 * K;

    float acc[4][4][4];
    #pragma unroll
    for (int mt = 0; mt < 4; mt++)
        #pragma unroll
        for (int nt = 0; nt < 4; nt++)
            #pragma unroll
            for (int r = 0; r < 4; r++) acc[mt][nt][r] = 0.f;

    auto load_stage = [&](int k0, int buf) {
        uint32_t* Ad = As + buf * G_WORDS;
        uint32_t* Bd = Bs + buf * G_WORDS;
        #pragma unroll
        for (int u = 0; u < 2; u++) {
            const int flat = tid + u * 256;
            const int r = flat >> 2;
            const int c = (flat & 3);
            cp_async16(smaddr(Ad + r * G_STR + c * 4), Ab + (size_t)r * K + k0 + c * 8);
            cp_async16(smaddr(Bd + r * G_STR + c * 4), Wb + (size_t)r * K + k0 + c * 8);
        }
    };

    const int NK = K / GBKH;
    load_stage(0, 0);
    cp_commit();

    for (int it = 0; it < NK; it++) {
        cp_wait0();
        __syncthreads();
        if (it + 1 < NK) { load_stage((it + 1) * GBKH, (it + 1) & 1); cp_commit(); }

        const uint32_t* As_s = As + (it & 1) * G_WORDS;
        const uint32_t* Bs_s = Bs + (it & 1) * G_WORDS;

        #pragma unroll
        for (int ch = 0; ch < 2; ch++) {
            const int ks2 = ch * 8;
            uint32_t af[4][4];
            #pragma unroll
            for (int mt = 0; mt < 4; mt++) {
                const int m0 = warpM * 64 + mt * 16;
                ldsm_x4(af[mt][0], af[mt][1], af[mt][2], af[mt][3],
                        smaddr(&As_s[(m0 + arow) * G_STR + ks2 + acol]));
            }
            uint32_t bf[4][2];
            #pragma unroll
            for (int np = 0; np < 2; np++) {
                const int n0 = warpN * 32 + np * 16;
                ldsm_x4(bf[np * 2][0], bf[np * 2][1], bf[np * 2 + 1][0], bf[np * 2 + 1][1],
                        smaddr(&Bs_s[(n0 + brow) * G_STR + ks2 + bcol]));
            }
            #pragma unroll
            for (int mt = 0; mt < 4; mt++)
                #pragma unroll
                for (int nt = 0; nt < 4; nt++)
                    mma_f16_16x8x16(acc[mt][nt][0], acc[mt][nt][1],
                                    acc[mt][nt][2], acc[mt][nt][3],
                                    af[mt][0], af[mt][1], af[mt][2], af[mt][3],
                                    bf[nt][0], bf[nt][1]);
        }
    }

    #pragma unroll
    for (int mt = 0; mt < 4; mt++) {
        #pragma unroll
        for (int nt = 0; nt < 4; nt++) {
            const int n = block_col * 128 + warpN * 32 + nt * 8 + lc * 2;
            #pragma unroll
            for (int half_ = 0; half_ < 2; half_++) {
                const int m = block_row * 128 + warpM * 64 + mt * 16 + lr + half_ * 8;
                const float v0 = acc[mt][nt][half_ * 2 + 0] + bias[n];
                const float v1 = acc[mt][nt][half_ * 2 + 1] + bias[n + 1];
                if (mode == 0) {
                    float* C = (float*)Cout;
                    *(float2*)&C[(size_t)m * N + n] = make_float2(v0, v1);
                } else {
                    const int b  = m >> 11;
                    const int s  = m & 2047;
                    const int h  = n >> 6;
                    const int dk = n & 63;
                    __half* C = (__half*)Cout;
                    if (mode == 1) {
                        *(__half2*)(C + (((size_t)(b * H_ + h)) * S_ + s) * DK_ + dk)
                            = __floats2half2_rn(v0 * out_scale, v1 * out_scale);
                    } else {
                        C[(((size_t)(b * H_ + h)) * DK_ + dk)     * S_ + s] = __float2half(v0);
                        C[(((size_t)(b * H_ + h)) * DK_ + dk + 1) * S_ + s] = __float2half(v1);
                    }
                }
            }
        }
    }
}

// fused QKV projections (grid.z selects tensor)
__global__ __launch_bounds__(256)
void gemm_qkv_kernel(const __half* __restrict__ qin, const __half* __restrict__ kin,
                     const __half* __restrict__ vin,
                     const __half* __restrict__ wq, const __half* __restrict__ wk,
                     const __half* __restrict__ wv,
                     const float* __restrict__ bq, const float* __restrict__ bk,
                     const float* __restrict__ bv,
                     __half* __restrict__ q, __half* __restrict__ k,
                     __half* __restrict__ vt)
{
    __shared__ uint32_t As[2 * G_WORDS];
    __shared__ uint32_t Bs[2 * G_WORDS];
    const int z = blockIdx.z;
    if (z == 0)      gemm_f16_body(qin, wq, bq, q,  1, QSCALE_, As, Bs);
    else if (z == 1) gemm_f16_body(kin, wk, bk, k,  1, 1.0f,    As, Bs);
    else             gemm_f16_body(vin, wv, bv, vt, 2, 1.0f,    As, Bs);
}

// output projection
__global__ __launch_bounds__(256)
void gemm_out_kernel(const __half* __restrict__ att, const __half* __restrict__ wo,
                     const float* __restrict__ bo, float* __restrict__ out)
{
    __shared__ uint32_t As[2 * G_WORDS];
    __shared__ uint32_t Bs[2 * G_WORDS];
    gemm_f16_body(att, wo, bo, out, 0, 1.0f, As, Bs);
}

// ---------------- fp16 tensor-core causal flash attention ----------------------
// 64 q-rows per block, 4 warps x 16 rows, double-buffered K / V^T tiles,
// P in registers; K/V fragments via ldmatrix.
#define FSTR 36                  // 32 half2 + 4 pad
#define FTILE (64 * FSTR)

__global__ __launch_bounds__(128)
void flash_attn_f16_kernel(const __half* __restrict__ q, const __half* __restrict__ k,
                           const __half* __restrict__ vt, __half* __restrict__ o)
{
    __shared__ uint32_t KsBuf[2][FTILE];
    __shared__ uint32_t VtBuf[2][FTILE];

    const int qt  = gridDim.x - 1 - blockIdx.x;   // big blocks first
    const int bh  = blockIdx.y;
    const int tid = threadIdx.x;
    const int warp = tid >> 5;
    const int lane = tid & 31;
    const int lr = lane >> 2;
    const int lc = lane & 3;
    const int q0 = qt * 64;
    const int mb = warp * 16;

    // ldmatrix B-operand lane selectors
    const int brow = ((lane >> 4) & 1) * 8 + (lane & 7);
    const int bcol = ((lane >> 3) & 1) * 4;

    const __half* qb  = q  + (size_t)bh * S_ * DK_;
    const __half* kb  = k  + (size_t)bh * S_ * DK_;
    const __half* vtb = vt + (size_t)bh * DK_ * S_;

    // stage Q tile (64x64h) into KsBuf[0]
    #pragma unroll
    for (int i = 0; i < 4; i++) {
        const int flat = tid + 128 * i;
        const int row = flat >> 3;
        const int c = flat & 7;
        cp_async16(smaddr(&KsBuf[0][row * FSTR + c * 4]),
                   qb + (size_t)(q0 + row) * DK_ + c * 8);
    }
    cp_commit();
    cp_wait0();
    __syncthreads();

    uint32_t qf[4][4];
    #pragma unroll
    for (int i = 0; i < 4; i++) {
        qf[i][0] = KsBuf[0][(mb + lr)     * FSTR + 8 * i + lc];
        qf[i][1] = KsBuf[0][(mb + 8 + lr) * FSTR + 8 * i + lc];
        qf[i][2] = KsBuf[0][(mb + lr)     * FSTR + 8 * i + 4 + lc];
        qf[i][3] = KsBuf[0][(mb + 8 + lr) * FSTR + 8 * i + 4 + lc];
    }
    __syncthreads();

    float oacc[8][4];
    #pragma unroll
    for (int nt = 0; nt < 8; nt++)
        #pragma unroll
        for (int c = 0; c < 4; c++) oacc[nt][c] = 0.f;
    float mrow[2] = { -INFINITY, -INFINITY };
    float lrow[2] = { 0.f, 0.f };

    auto load_k = [&](int k0, int buf) {
        #pragma unroll
        for (int i = 0; i < 4; i++) {
            const int flat = tid + 128 * i;
            const int row = flat >> 3;
            const int c = flat & 7;
            cp_async16(smaddr(&KsBuf[buf][row * FSTR + c * 4]),
                       kb + (size_t)(k0 + row) * DK_ + c * 8);
        }
    };
    auto load_v = [&](int k0, int buf) {
        #pragma unroll
        for (int i = 0; i < 4; i++) {
            const int flat = tid + 128 * i;
            const int row = flat >> 3;
            const int c = flat & 7;
            cp_async16(smaddr(&VtBuf[buf][row * FSTR + c * 4]),
                       vtb + (size_t)row * S_ + k0 + c * 8);
        }
    };

    const int NT = qt + 1;
    load_k(0, 0);
    load_v(0, 0);
    cp_commit();

    for (int kt = 0; kt < NT; kt++) {
        const int cur = kt & 1;
        cp_wait0();
        __syncthreads();
        if (kt + 1 < NT) {
            load_k((kt + 1) * 64, cur ^ 1);
            load_v((kt + 1) * 64, cur ^ 1);
            cp_commit();
        }
        const int k0 = kt * 64;
        const uint32_t* Ks = KsBuf[cur];
        const uint32_t* Vt = VtBuf[cur];

        // ---- S = Q @ K^T (ldmatrix for K fragments; 2 n-tiles per x4) ----
        float s[8][4];
        #pragma unroll
        for (int nt = 0; nt < 8; nt++)
            s[nt][0] = s[nt][1] = s[nt][2] = s[nt][3] = 0.f;
        #pragma unroll
        for (int i = 0; i < 4; i++) {
            #pragma unroll
            for (int p = 0; p < 4; p++) {
                uint32_t b00, b01, b10, b11;
                ldsm_x4(b00, b01, b10, b11,
                        smaddr(&Ks[(p * 16 + brow) * FSTR + 8 * i + bcol]));
                mma_f16_16x8x16(s[2*p][0], s[2*p][1], s[2*p][2], s[2*p][3],
                                qf[i][0], qf[i][1], qf[i][2], qf[i][3], b00, b01);
                mma_f16_16x8x16(s[2*p+1][0], s[2*p+1][1], s[2*p+1][2], s[2*p+1][3],
                                qf[i][0], qf[i][1], qf[i][2], qf[i][3], b10, b11);
            }
        }

        // ---- causal mask (diagonal tile only) ----
        if (kt == qt) {
            const int r0 = q0 + mb + lr;
            const int r1 = r0 + 8;
            #pragma unroll
            for (int nt = 0; nt < 8; nt++) {
                const int cg = k0 + nt * 8 + 2 * lc;
                if (cg     > r0) s[nt][0] = -1e30f;
                if (cg + 1 > r0) s[nt][1] = -1e30f;
                if (cg     > r1) s[nt][2] = -1e30f;
                if (cg + 1 > r1) s[nt][3] = -1e30f;
            }
        }

        // ---- online softmax (base-2) ----
        float m0 = -INFINITY, m1 = -INFINITY;
        #pragma unroll
        for (int nt = 0; nt < 8; nt++) {
            m0 = fmaxf(m0, fmaxf(s[nt][0], s[nt][1]));
            m1 = fmaxf(m1, fmaxf(s[nt][2], s[nt][3]));
        }
        m0 = fmaxf(m0, __shfl_xor_sync(0xffffffffu, m0, 1));
        m0 = fmaxf(m0, __shfl_xor_sync(0xffffffffu, m0, 2));
        m1 = fmaxf(m1, __shfl_xor_sync(0xffffffffu, m1, 1));
        m1 = fmaxf(m1, __shfl_xor_sync(0xffffffffu, m1, 2));

        const float mnew0 = fmaxf(mrow[0], m0);
        const float mnew1 = fmaxf(mrow[1], m1);
        const float alpha0 = fexp2(mrow[0] - mnew0);
        const float alpha1 = fexp2(mrow[1] - mnew1);
        float ls0 = 0.f, ls1 = 0.f;
        #pragma unroll
        for (int nt = 0; nt < 8; nt++) {
            s[nt][0] = fexp2(s[nt][0] - mnew0);
            s[nt][1] = fexp2(s[nt][1] - mnew0);
            s[nt][2] = fexp2(s[nt][2] - mnew1);
            s[nt][3] = fexp2(s[nt][3] - mnew1);
            ls0 += s[nt][0] + s[nt][1];
            ls1 += s[nt][2] + s[nt][3];
        }
        ls0 += __shfl_xor_sync(0xffffffffu, ls0, 1);
        ls0 += __shfl_xor_sync(0xffffffffu, ls0, 2);
        ls1 += __shfl_xor_sync(0xffffffffu, ls1, 1);
        ls1 += __shfl_xor_sync(0xffffffffu, ls1, 2);
        lrow[0] = lrow[0] * alpha0 + ls0;
        lrow[1] = lrow[1] * alpha1 + ls1;
        mrow[0] = mnew0;
        mrow[1] = mnew1;
        #pragma unroll
        for (int nt = 0; nt < 8; nt++) {
            oacc[nt][0] *= alpha0; oacc[nt][1] *= alpha0;
            oacc[nt][2] *= alpha1; oacc[nt][3] *= alpha1;
        }

        // ---- O += P @ V : P packed from registers, V via ldmatrix ----
        #pragma unroll
        for (int i = 0; i < 4; i++) {
            const uint32_t pf0 = h2u(__floats2half2_rn(s[2 * i][0],     s[2 * i][1]));
            const uint32_t pf1 = h2u(__floats2half2_rn(s[2 * i][2],     s[2 * i][3]));
            const uint32_t pf2 = h2u(__floats2half2_rn(s[2 * i + 1][0], s[2 * i + 1][1]));
            const uint32_t pf3 = h2u(__floats2half2_rn(s[2 * i + 1][2], s[2 * i + 1][3]));
            #pragma unroll
            for (int p = 0; p < 4; p++) {
                uint32_t b00, b01, b10, b11;
                ldsm_x4(b00, b01, b10, b11,
                        smaddr(&Vt[(p * 16 + brow) * FSTR + 8 * i + bcol]));
                mma_f16_16x8x16(oacc[2*p][0], oacc[2*p][1], oacc[2*p][2], oacc[2*p][3],
                                pf0, pf1, pf2, pf3, b00, b01);
                mma_f16_16x8x16(oacc[2*p+1][0], oacc[2*p+1][1], oacc[2*p+1][2], oacc[2*p+1][3],
                                pf0, pf1, pf2, pf3, b10, b11);
            }
        }
    }

    // ---- finalize & write fp16 to [B,S,D] ----
    const float inv0 = 1.f / lrow[0];
    const float inv1 = 1.f / lrow[1];
    const int b = bh >> 4;
    const int h = bh & 15;
    const int r0 = q0 + mb + lr;
    __half* ob0 = o + ((size_t)b * S_ + r0)     * D_ + h * DK_;
    __half* ob1 = o + ((size_t)b * S_ + r0 + 8) * D_ + h * DK_;
    #pragma unroll
    for (int nt = 0; nt < 8; nt++) {
        const int c = nt * 8 + 2 * lc;
        *(__half2*)(ob0 + c) = __floats2half2_rn(oacc[nt][0] * inv0, oacc[nt][1] * inv0);
        *(__half2*)(ob1 + c) = __floats2half2_rn(oacc[nt][2] * inv1, oacc[nt][3] * inv1);
    }
}

// ---------------- launch ------------------------------------------------------
extern "C" void kernel_launch(void* const* d_in, const int* in_sizes, int n_in,
                              void* d_out, int out_size)
{
    const float* Q  = (const float*)d_in[0];
    const float* K  = (const float*)d_in[1];
    const float* V  = (const float*)d_in[2];
    const float* Wq = (const float*)d_in[3];
    const float* bq = (const float*)d_in[4];
    const float* Wk = (const float*)d_in[5];
    const float* bk = (const float*)d_in[6];
    const float* Wv = (const float*)d_in[7];
    const float* bv = (const float*)d_in[8];
    const float* Wo = (const float*)d_in[9];
    const float* bo = (const float*)d_in[10];
    // d_in[11] = mask (causal, known statically; ignored)

    __half *qin, *kin, *vin, *wq, *wk, *wv, *wo, *q, *k, *vt, *att;
    cudaGetSymbolAddress((void**)&qin, g_qin);
    cudaGetSymbolAddress((void**)&kin, g_kin);
    cudaGetSymbolAddress((void**)&vin, g_vin);
    cudaGetSymbolAddress((void**)&wq,  g_wq);
    cudaGetSymbolAddress((void**)&wk,  g_wk);
    cudaGetSymbolAddress((void**)&wv,  g_wv);
    cudaGetSymbolAddress((void**)&wo,  g_wo);
    cudaGetSymbolAddress((void**)&q,   g_q);
    cudaGetSymbolAddress((void**)&k,   g_k);
    cudaGetSymbolAddress((void**)&vt,  g_vt);
    cudaGetSymbolAddress((void**)&att, g_att);

    // fused conversions
    const int n4_in = (B_ * S_ * D_) / 4;
    const dim3 c3_grid((n4_in + 255) / 256, 3);
    conv_h3_kernel<<<c3_grid, 256>>>((const float4*)Q, (const float4*)K,
                                     (const float4*)V, (uint2*)qin, (uint2*)kin,
                                     (uint2*)vin, n4_in);
    const dim3 wt_grid(D_ / 32, D_ / 32, 4);
    const dim3 wt_block(32, 8);
    convT_w4_kernel<<<wt_grid, wt_block>>>(Wq, Wk, Wv, Wo, wq, wk, wv, wo);

    // fused QKV projections (Q pre-scaled into log2 domain; V transposed)
    const dim3 qkv_grid(D_ / 128, M_ROWS / 128, 3);   // (8, 64, 3)
    gemm_qkv_kernel<<<qkv_grid, 256>>>(qin, kin, vin, wq, wk, wv,
                                       bq, bk, bv, q, k, vt);

    // causal flash attention -> fp16 [B,S,D]
    const dim3 fa_grid(S_ / 64, B_ * H_);             // (32, 64)
    flash_attn_f16_kernel<<<fa_grid, 128>>>(q, k, vt, att);

    // output projection -> d_out (fp32)
    const dim3 out_grid(D_ / 128, M_ROWS / 128);
    gemm_out_kernel<<<out_grid, 256>>>(att, wo, bo, (float*)d_out);
}